// round 2
// baseline (speedup 1.0000x reference)
#include <cuda_runtime.h>
#include <math.h>

#define B 4
#define T 4096
#define S 4096
#define E 512
#define H 64

// scale = H^-0.5 = 0.125, folded into the q table.
#define SCALE 0.125f

// Scratch (device globals: allocation-free per harness rules)
__device__ float g_q[B * T * H];     // 4 MB : SCALE * tanh(x*qw + qb)
__device__ float g_k[B * S * H];     // 4 MB : tanh(emb @ kw^T + kb)
__device__ float g_v[B * S * H];     // 4 MB : tanh(emb @ vw^T), later v/denom in place
__device__ float g_denom[B * S];     // 64 KB

// ---------------------------------------------------------------------------
// Kernel A: q table. g_q[(b*T+t)*H+h] = SCALE * tanh(x[b,t]*qw[h] + qb[h])
// ---------------------------------------------------------------------------
__global__ __launch_bounds__(256) void q_kernel(const float* __restrict__ x,
                                                const float* __restrict__ qw,
                                                const float* __restrict__ qb) {
    int idx = blockIdx.x * 256 + threadIdx.x;   // over B*T*H
    int h  = idx & (H - 1);
    int bt = idx >> 6;
    g_q[idx] = SCALE * tanhf(x[bt] * qw[h] + qb[h]);
}

// ---------------------------------------------------------------------------
// Kernel B: k and v. Block = 64 rows (b,s) x 64 h; loop E in chunks of 32.
// 256 threads as 16x16, each owns a 4(row) x 4(h) micro-tile for both k and v.
// ---------------------------------------------------------------------------
__global__ __launch_bounds__(256) void kv_kernel(const float* __restrict__ emb,
                                                 const float* __restrict__ kw,
                                                 const float* __restrict__ kb,
                                                 const float* __restrict__ vw) {
    __shared__ __align__(16) float embT[32][68];   // [e][row]
    __shared__ __align__(16) float kwT[32][68];    // [e][h]
    __shared__ __align__(16) float vwT[32][68];    // [e][h]

    const int r0  = blockIdx.x * 64;               // global (b*S+s) row base
    const int tid = threadIdx.x;
    const int ty  = tid >> 4;                      // 0..15 -> row group
    const int tx  = tid & 15;                      // 0..15 -> h group

    float ak[4][4] = {};
    float av[4][4] = {};

    for (int e0 = 0; e0 < E; e0 += 32) {
        __syncthreads();
        for (int j = tid; j < 64 * 32; j += 256) {
            int r = j >> 5, e = j & 31;
            embT[e][r] = emb[(size_t)(r0 + r) * E + e0 + e];
            kwT[e][r]  = kw[(size_t)r * E + e0 + e];
            vwT[e][r]  = vw[(size_t)r * E + e0 + e];
        }
        __syncthreads();
#pragma unroll 8
        for (int e = 0; e < 32; e++) {
            float4 a  = *(const float4*)&embT[e][4 * ty];
            float4 k4 = *(const float4*)&kwT[e][4 * tx];
            float4 v4 = *(const float4*)&vwT[e][4 * tx];
            float ar[4] = {a.x, a.y, a.z, a.w};
            float kr[4] = {k4.x, k4.y, k4.z, k4.w};
            float vr[4] = {v4.x, v4.y, v4.z, v4.w};
#pragma unroll
            for (int i = 0; i < 4; i++)
#pragma unroll
                for (int j = 0; j < 4; j++) {
                    ak[i][j] += ar[i] * kr[j];
                    av[i][j] += ar[i] * vr[j];
                }
        }
    }

#pragma unroll
    for (int i = 0; i < 4; i++) {
        int row = r0 + 4 * ty + i;
#pragma unroll
        for (int j = 0; j < 4; j++) {
            int h = 4 * tx + j;
            g_k[(size_t)row * H + h] = tanhf(ak[i][j] + kb[h]);
            g_v[(size_t)row * H + h] = tanhf(av[i][j]);
        }
    }
}

// ---------------------------------------------------------------------------
// Kernel C: denom[b,s] = sum_t exp(L[t,s]).  Block = 64 s cols, loop all T.
// ---------------------------------------------------------------------------
__global__ __launch_bounds__(256) void denom_kernel() {
    __shared__ __align__(16) float kT[64][68];  // [h][s]
    __shared__ __align__(16) float qT[64][68];  // [h][t]
    __shared__ float dsh[64];

    const int b   = blockIdx.y;
    const int s0  = blockIdx.x * 64;
    const int tid = threadIdx.x;
    const int ty  = tid >> 4;   // t group
    const int tx  = tid & 15;   // s group

    for (int j = tid; j < 4096; j += 256) {
        int r = j >> 6, h = j & 63;
        kT[h][r] = g_k[(size_t)(b * S + s0 + r) * H + h];
    }
    if (tid < 64) dsh[tid] = 0.0f;

    float dsum[4] = {0.f, 0.f, 0.f, 0.f};

    for (int t0 = 0; t0 < T; t0 += 64) {
        __syncthreads();
        for (int j = tid; j < 4096; j += 256) {
            int r = j >> 6, h = j & 63;
            qT[h][r] = g_q[(size_t)(b * T + t0 + r) * H + h];
        }
        __syncthreads();

        float L[4][4] = {};
#pragma unroll 8
        for (int h = 0; h < 64; h++) {
            float4 qa = *(const float4*)&qT[h][4 * ty];
            float4 ka = *(const float4*)&kT[h][4 * tx];
            float qr[4] = {qa.x, qa.y, qa.z, qa.w};
            float kr[4] = {ka.x, ka.y, ka.z, ka.w};
#pragma unroll
            for (int i = 0; i < 4; i++)
#pragma unroll
                for (int j = 0; j < 4; j++) L[i][j] += qr[i] * kr[j];
        }
#pragma unroll
        for (int i = 0; i < 4; i++)
#pragma unroll
            for (int j = 0; j < 4; j++) dsum[j] += __expf(L[i][j]);
    }

    __syncthreads();
#pragma unroll
    for (int j = 0; j < 4; j++) atomicAdd(&dsh[4 * tx + j], dsum[j]);
    __syncthreads();
    if (tid < 64) g_denom[b * S + s0 + tid] = dsh[tid];
}

// ---------------------------------------------------------------------------
// Kernel D: v' = v / denom (in place)
// ---------------------------------------------------------------------------
__global__ __launch_bounds__(256) void scale_v_kernel() {
    int idx = blockIdx.x * 256 + threadIdx.x;  // over B*S*H
    g_v[idx] = g_v[idx] / g_denom[idx >> 6];
}

// ---------------------------------------------------------------------------
// Kernel E: out[b,t] = pb + sum_h pw[h]*tanh( sum_s exp(L[t,s]) * v'[s,h] )
// Block = 64 t rows x all 64 h; loop s in chunks of 64.
// Stage 1: L tile -> exp -> Wt smem (transposed). Stage 2: out += Wt^T @ v'.
// ---------------------------------------------------------------------------
#define SMEM_E ((4 * 64 * 68 + 64 * 17) * 4)

__global__ __launch_bounds__(256) void out_kernel(const float* __restrict__ pw,
                                                  const float* __restrict__ pb,
                                                  float* __restrict__ out) {
    extern __shared__ __align__(16) float sm[];
    float(*qT)[68]  = (float(*)[68])sm;                  // [h][t]
    float(*kT)[68]  = (float(*)[68])(sm + 1 * 64 * 68);  // [h][s]
    float(*Wt)[68]  = (float(*)[68])(sm + 2 * 64 * 68);  // [s][t]
    float(*vs)[68]  = (float(*)[68])(sm + 3 * 64 * 68);  // [s][h]
    float(*red)[17] = (float(*)[17])(sm + 4 * 64 * 68);  // [t][tx]

    const int b   = blockIdx.y;
    const int t0  = blockIdx.x * 64;
    const int tid = threadIdx.x;
    const int ty  = tid >> 4;   // t group (stage1), t group (stage2)
    const int tx  = tid & 15;   // s group (stage1), h group (stage2)

    for (int j = tid; j < 4096; j += 256) {
        int t = j >> 6, h = j & 63;
        qT[h][t] = g_q[(size_t)(b * T + t0 + t) * H + h];
    }

    float ao[4][4] = {};

    for (int s0 = 0; s0 < S; s0 += 64) {
        __syncthreads();
        for (int j = tid; j < 4096; j += 256) {
            int s = j >> 6, h = j & 63;
            float kv = g_k[(size_t)(b * S + s0 + s) * H + h];
            float vv = g_v[(size_t)(b * S + s0 + s) * H + h];
            kT[h][s] = kv;
            vs[s][h] = vv;
        }
        __syncthreads();

        // Stage 1: L[t,s] tile, exp, store transposed
        float L[4][4] = {};
#pragma unroll 8
        for (int h = 0; h < 64; h++) {
            float4 qa = *(const float4*)&qT[h][4 * ty];
            float4 ka = *(const float4*)&kT[h][4 * tx];
            float qr[4] = {qa.x, qa.y, qa.z, qa.w};
            float kr[4] = {ka.x, ka.y, ka.z, ka.w};
#pragma unroll
            for (int i = 0; i < 4; i++)
#pragma unroll
                for (int j = 0; j < 4; j++) L[i][j] += qr[i] * kr[j];
        }
#pragma unroll
        for (int i = 0; i < 4; i++)
#pragma unroll
            for (int j = 0; j < 4; j++) Wt[4 * tx + j][4 * ty + i] = __expf(L[i][j]);
        __syncthreads();

        // Stage 2: ao[t,h] += sum_s W[t,s] * v'[s,h]
#pragma unroll 8
        for (int s = 0; s < 64; s++) {
            float4 w4 = *(const float4*)&Wt[s][4 * ty];
            float4 v4 = *(const float4*)&vs[s][4 * tx];
            float wr[4] = {w4.x, w4.y, w4.z, w4.w};
            float vr[4] = {v4.x, v4.y, v4.z, v4.w};
#pragma unroll
            for (int i = 0; i < 4; i++)
#pragma unroll
                for (int j = 0; j < 4; j++) ao[i][j] += wr[i] * vr[j];
        }
    }

    // Epilogue: tanh, project with pw, reduce over h
#pragma unroll
    for (int i = 0; i < 4; i++) {
        float part = 0.0f;
#pragma unroll
        for (int j = 0; j < 4; j++) part += tanhf(ao[i][j]) * pw[4 * tx + j];
        red[4 * ty + i][tx] = part;
    }
    __syncthreads();
    if (tid < 64) {
        float ssum = pb[0];
#pragma unroll
        for (int k2 = 0; k2 < 16; k2++) ssum += red[tid][k2];
        out[(size_t)b * T + t0 + tid] = ssum;
    }
}

// ---------------------------------------------------------------------------
extern "C" void kernel_launch(void* const* d_in, const int* in_sizes, int n_in,
                              void* d_out, int out_size) {
    const float* x   = (const float*)d_in[0];
    const float* emb = (const float*)d_in[1];
    const float* kw  = (const float*)d_in[2];
    const float* kb  = (const float*)d_in[3];
    const float* qw  = (const float*)d_in[4];
    const float* qb  = (const float*)d_in[5];
    const float* vw  = (const float*)d_in[6];
    const float* pw  = (const float*)d_in[7];
    const float* pb  = (const float*)d_in[8];
    float* out = (float*)d_out;

    cudaFuncSetAttribute(out_kernel, cudaFuncAttributeMaxDynamicSharedMemorySize, SMEM_E);

    q_kernel<<<(B * T * H) / 256, 256>>>(x, qw, qb);
    kv_kernel<<<(B * S) / 64, 256>>>(emb, kw, kb, vw);
    denom_kernel<<<dim3(S / 64, B), 256>>>();
    scale_v_kernel<<<(B * S * H) / 256, 256>>>();
    out_kernel<<<dim3(T / 64, B), 256, SMEM_E>>>(pw, pb, out);
}